// round 7
// baseline (speedup 1.0000x reference)
#include <cuda_runtime.h>
#include <cuda_bf16.h>
#include <math.h>

#define FULL_MASK 0xffffffffu

#define BATCH   32
#define DIM     4096
#define NQ      32
#define NKV     8
#define HD      128
#define QKV_N   6144
#define REP     4
#define KSPLIT  16
#define KLEN    (DIM / KSPLIT)   // 256
#define TSPLIT  16
#define CHUNK_MAX 128            // ceil(2048 / TSPLIT)

// Scratch (device globals; no allocation allowed)
__device__ float g_qkv[BATCH * QKV_N];                    // post-reduce, post-RoPE
__device__ float g_att[BATCH * DIM];                      // attention output, pre-wo
__device__ float g_part_qkv[KSPLIT][BATCH][QKV_N];        // split-K partials
__device__ float g_part_o[KSPLIT][BATCH][DIM];
__device__ float g_attp[TSPLIT][BATCH][NKV][REP][HD];     // split-T partial A*V (unnormalized)
__device__ float g_attm[TSPLIT][BATCH][NKV][REP];         // split-T local max
__device__ float g_atts[TSPLIT][BATCH][NKV][REP];         // split-T local expsum

// ---------------- packed fp32x2 helpers (Blackwell) ----------------
__device__ __forceinline__ unsigned long long pack2(float lo, float hi) {
    unsigned long long r;
    asm("mov.b64 %0, {%1, %2};" : "=l"(r) : "f"(lo), "f"(hi));
    return r;
}
__device__ __forceinline__ void fma2(unsigned long long& d, unsigned long long a, unsigned long long b) {
    asm("fma.rn.f32x2 %0, %1, %2, %0;" : "+l"(d) : "l"(a), "l"(b));
}
__device__ __forceinline__ float2 unpack2(unsigned long long v) {
    float lo, hi;
    asm("mov.b64 {%0, %1}, %2;" : "=f"(lo), "=f"(hi) : "l"(v));
    return make_float2(lo, hi);
}
__device__ __forceinline__ float4 ldcs4(const float* p) {
    float4 v;
    asm("ld.global.cs.v4.f32 {%0,%1,%2,%3}, [%4];"
        : "=f"(v.x), "=f"(v.y), "=f"(v.z), "=f"(v.w) : "l"(p));
    return v;
}

// ---------------- Split-K skinny GEMM tile (proven shape) ----------------
__device__ __forceinline__ void gemm_tile(const float* __restrict__ A,
                                          const float* __restrict__ W,
                                          float* __restrict__ C,
                                          int K, int ldc, int wrow0, int ccol0,
                                          int kbeg)
{
    __shared__ __align__(16) float As[32][34];   // [kk][m]
    __shared__ float Ws[32][65];                 // [kk][n]

    const int tid   = threadIdx.x;
    const int c     = tid & 31;
    const int rbase = (tid >> 5) << 3;           // 0,8,16,24

    unsigned long long acc[4][2];
#pragma unroll
    for (int p = 0; p < 4; p++) { acc[p][0] = 0ull; acc[p][1] = 0ull; }

    for (int k0 = kbeg; k0 < kbeg + KLEN; k0 += 32) {
#pragma unroll
        for (int j = 0; j < 2; j++) {
            int e  = tid + j * 128;
            int m  = e >> 3;
            int kk = (e & 7) * 4;
            float4 v = *reinterpret_cast<const float4*>(&A[(size_t)m * K + k0 + kk]);
            As[kk + 0][m] = v.x; As[kk + 1][m] = v.y;
            As[kk + 2][m] = v.z; As[kk + 3][m] = v.w;
        }
#pragma unroll
        for (int j = 0; j < 4; j++) {
            int e  = tid + j * 128;
            int n  = e >> 3;
            int kk = (e & 7) * 4;
            float4 v = *reinterpret_cast<const float4*>(&W[(size_t)(wrow0 + n) * K + k0 + kk]);
            Ws[kk + 0][n] = v.x; Ws[kk + 1][n] = v.y;
            Ws[kk + 2][n] = v.z; Ws[kk + 3][n] = v.w;
        }
        __syncthreads();

#pragma unroll
        for (int kk = 0; kk < 32; kk++) {
            const unsigned long long* ap =
                reinterpret_cast<const unsigned long long*>(&As[kk][rbase]);
            unsigned long long a0 = ap[0], a1 = ap[1], a2 = ap[2], a3 = ap[3];
            float w0 = Ws[kk][c];
            float w1 = Ws[kk][c + 32];
            unsigned long long W0 = pack2(w0, w0);
            unsigned long long W1 = pack2(w1, w1);
            fma2(acc[0][0], a0, W0); fma2(acc[1][0], a1, W0);
            fma2(acc[2][0], a2, W0); fma2(acc[3][0], a3, W0);
            fma2(acc[0][1], a0, W1); fma2(acc[1][1], a1, W1);
            fma2(acc[2][1], a2, W1); fma2(acc[3][1], a3, W1);
        }
        __syncthreads();
    }

#pragma unroll
    for (int p = 0; p < 4; p++) {
#pragma unroll
        for (int cc = 0; cc < 2; cc++) {
            float2 v = unpack2(acc[p][cc]);
            int m   = rbase + 2 * p;
            int col = ccol0 + c + 32 * cc;
            C[(size_t)m * ldc + col]       = v.x;
            C[(size_t)(m + 1) * ldc + col] = v.y;
        }
    }
}

__global__ void gemm_qkv_kernel(const float* __restrict__ x,
                                const float* __restrict__ wq,
                                const float* __restrict__ wk,
                                const float* __restrict__ wv)
{
    int n0 = blockIdx.x * 64;
    int kbeg = blockIdx.y * KLEN;
    const float* W;
    int wrow0;
    if (n0 < 4096)      { W = wq; wrow0 = n0; }
    else if (n0 < 5120) { W = wk; wrow0 = n0 - 4096; }
    else                { W = wv; wrow0 = n0 - 5120; }
    gemm_tile(x, W, &g_part_qkv[blockIdx.y][0][0], DIM, QKV_N, wrow0, n0, kbeg);
}

__global__ void gemm_o_kernel(const float* __restrict__ wo)
{
    int n0 = blockIdx.x * 64;
    int kbeg = blockIdx.y * KLEN;
    gemm_tile(g_att, wo, &g_part_o[blockIdx.y][0][0], DIM, DIM, n0, n0, kbeg);
}

// ---------------- QKV reduce + fused RoPE ----------------
__global__ void reduce_qkv_rope(const float* __restrict__ cosv,
                                const float* __restrict__ sinv)
{
    int idx = blockIdx.x * 256 + threadIdx.x;
    if (idx >= BATCH * (QKV_N / 2)) return;
    int b  = idx / (QKV_N / 2);
    int pr = idx - b * (QKV_N / 2);
    int col = pr * 2;

    float sx = 0.f, sy = 0.f;
#pragma unroll
    for (int ks = 0; ks < KSPLIT; ks++) {
        float2 v = *reinterpret_cast<const float2*>(&g_part_qkv[ks][b][col]);
        sx += v.x; sy += v.y;
    }
    float2 o;
    if (col < 5120) {
        int d2 = (col & (HD - 1)) >> 1;
        float c = cosv[d2], s = sinv[d2];
        o.x = sx * c - sy * s;
        o.y = sx * s + sy * c;
    } else {
        o.x = sx; o.y = sy;
    }
    *reinterpret_cast<float2*>(&g_qkv[(size_t)b * QKV_N + col]) = o;
}

__global__ void reduce_o(float* __restrict__ out)
{
    int idx = blockIdx.x * 256 + threadIdx.x;
    if (idx >= BATCH * (DIM / 2)) return;
    int b  = idx / (DIM / 2);
    int pr = idx - b * (DIM / 2);
    int col = pr * 2;
    float sx = 0.f, sy = 0.f;
#pragma unroll
    for (int ks = 0; ks < KSPLIT; ks++) {
        float2 v = *reinterpret_cast<const float2*>(&g_part_o[ks][b][col]);
        sx += v.x; sy += v.y;
    }
    *reinterpret_cast<float2*>(&out[(size_t)b * DIM + col]) = make_float2(sx, sy);
}

// ---------------- Attention partials: grid (NKV, BATCH, TSPLIT), 512 thr ----------------
__global__ void __launch_bounds__(512, 3)
attn_part_kernel(const float* __restrict__ cache_k,
                 const float* __restrict__ cache_v,
                 const int* __restrict__ sp_ptr,
                 int max_seq)
{
    const int g    = blockIdx.x;
    const int b    = blockIdx.y;
    const int ts   = blockIdx.z;
    const int tid  = threadIdx.x;     // 0..511
    const int lane = tid & 31;
    const int w    = tid >> 5;        // 0..15
    const int sp   = *sp_ptr;
    const int T    = sp + 1;
    const int chunk = (T + TSPLIT - 1) / TSPLIT;
    const int t0   = ts * chunk;
    const int t1   = min(t0 + chunk, T);

    // V-phase / output thread mapping
    const int d4 = tid & 31;          // float4 column (d = 4*d4..4*d4+3)
    const int rv = (tid >> 5) & 3;    // rep
    const int tg = tid >> 7;          // 0..3 t-group

    if (t0 >= T) {     // empty split
        if (tid < REP) { g_attm[ts][b][g][tid] = -3.0e38f; g_atts[ts][b][g][tid] = 0.f; }
        if (tg == 0)
            *reinterpret_cast<float4*>(&g_attp[ts][b][g][rv][d4 * 4]) =
                make_float4(0.f, 0.f, 0.f, 0.f);
        return;
    }
    const int n = t1 - t0;            // <= CHUNK_MAX

    __shared__ float sc[REP][CHUNK_MAX];
    __shared__ float q4s[REP][HD];
    __shared__ float redm[REP][4];
    __shared__ float reds[REP][4];
    __shared__ float rmax[REP];
    __shared__ float rsum[REP];
    __shared__ __align__(16) float4 vred[4][REP][32];   // 8KB tg-reduction

    for (int i = tid; i < REP * HD; i += 512) {
        int rr = i >> 7, dd = i & (HD - 1);
        q4s[rr][dd] = g_qkv[(size_t)b * QKV_N + (g * REP + rr) * HD + dd];
    }
    __syncthreads();

    float4 q0 = reinterpret_cast<const float4*>(q4s[0])[lane];
    float4 q1 = reinterpret_cast<const float4*>(q4s[1])[lane];
    float4 q2 = reinterpret_cast<const float4*>(q4s[2])[lane];
    float4 q3 = reinterpret_cast<const float4*>(q4s[3])[lane];

    const float* knew = &g_qkv[(size_t)b * QKV_N + 4096 + g * HD];
    const float* vnew = &g_qkv[(size_t)b * QKV_N + 5120 + g * HD];
    const float scale = 0.08838834764831845f;   // 1/sqrt(128)

    // ---- scores: 2 t per warp per iteration, batched shuffles ----
    for (int t = t0 + 2 * w; t < t1; t += 32) {
        const int ta = t;
        const int tb = t + 1;
        const bool hb = (tb < t1);
        const float* kpa = (ta < sp)
            ? &cache_k[(((size_t)b * max_seq + ta) * NKV + g) * HD]
            : knew;
        float4 ka = (ta < sp) ? ldcs4(kpa + lane * 4)
                              : reinterpret_cast<const float4*>(kpa)[lane];
        float4 kb;
        if (hb) {
            const float* kpb = (tb < sp)
                ? &cache_k[(((size_t)b * max_seq + tb) * NKV + g) * HD]
                : knew;
            kb = (tb < sp) ? ldcs4(kpb + lane * 4)
                           : reinterpret_cast<const float4*>(kpb)[lane];
        } else {
            kb = make_float4(0.f, 0.f, 0.f, 0.f);
        }

        float p0a = q0.x*ka.x + q0.y*ka.y + q0.z*ka.z + q0.w*ka.w;
        float p1a = q1.x*ka.x + q1.y*ka.y + q1.z*ka.z + q1.w*ka.w;
        float p2a = q2.x*ka.x + q2.y*ka.y + q2.z*ka.z + q2.w*ka.w;
        float p3a = q3.x*ka.x + q3.y*ka.y + q3.z*ka.z + q3.w*ka.w;
        float p0b = q0.x*kb.x + q0.y*kb.y + q0.z*kb.z + q0.w*kb.w;
        float p1b = q1.x*kb.x + q1.y*kb.y + q1.z*kb.z + q1.w*kb.w;
        float p2b = q2.x*kb.x + q2.y*kb.y + q2.z*kb.z + q2.w*kb.w;
        float p3b = q3.x*kb.x + q3.y*kb.y + q3.z*kb.z + q3.w*kb.w;
#pragma unroll
        for (int off = 16; off; off >>= 1) {
            p0a += __shfl_xor_sync(FULL_MASK, p0a, off);
            p1a += __shfl_xor_sync(FULL_MASK, p1a, off);
            p2a += __shfl_xor_sync(FULL_MASK, p2a, off);
            p3a += __shfl_xor_sync(FULL_MASK, p3a, off);
            p0b += __shfl_xor_sync(FULL_MASK, p0b, off);
            p1b += __shfl_xor_sync(FULL_MASK, p1b, off);
            p2b += __shfl_xor_sync(FULL_MASK, p2b, off);
            p3b += __shfl_xor_sync(FULL_MASK, p3b, off);
        }
        if (lane == 0) {
            sc[0][ta - t0] = p0a * scale; sc[1][ta - t0] = p1a * scale;
            sc[2][ta - t0] = p2a * scale; sc[3][ta - t0] = p3a * scale;
            if (hb) {
                sc[0][tb - t0] = p0b * scale; sc[1][tb - t0] = p1b * scale;
                sc[2][tb - t0] = p2b * scale; sc[3][tb - t0] = p3b * scale;
            }
        }
    }
    __syncthreads();

    // ---- local softmax: all 4 reps in parallel (128 threads per rep) ----
    {
        const int rr  = tid >> 7;
        const int tt  = tid & 127;
        const int wq4 = (tid >> 5) & 3;

        float mv = (tt < n) ? sc[rr][tt] : -3.0e38f;
#pragma unroll
        for (int off = 16; off; off >>= 1) mv = fmaxf(mv, __shfl_xor_sync(FULL_MASK, mv, off));
        if (lane == 0) redm[rr][wq4] = mv;
        __syncthreads();
        float m = fmaxf(fmaxf(redm[rr][0], redm[rr][1]),
                        fmaxf(redm[rr][2], redm[rr][3]));

        float e = 0.f;
        if (tt < n) {
            e = __expf(sc[rr][tt] - m);
            sc[rr][tt] = e;
        }
        float s = e;
#pragma unroll
        for (int off = 16; off; off >>= 1) s += __shfl_xor_sync(FULL_MASK, s, off);
        if (lane == 0) reds[rr][wq4] = s;
        __syncthreads();
        if (tt == 0) {
            rmax[rr] = m;
            rsum[rr] = reds[rr][0] + reds[rr][1] + reds[rr][2] + reds[rr][3];
        }
    }
    __syncthreads();

    // ---- partial A @ V: thread (tg, rv, d4), float4 loads, t strided by 4 ----
    float4 a4 = make_float4(0.f, 0.f, 0.f, 0.f);
#pragma unroll 4
    for (int t = t0 + tg; t < t1; t += 4) {
        float4 v = (t < sp)
            ? ldcs4(&cache_v[(((size_t)b * max_seq + t) * NKV + g) * HD + d4 * 4])
            : reinterpret_cast<const float4*>(vnew)[d4];
        float wgt = sc[rv][t - t0];
        a4.x += wgt * v.x; a4.y += wgt * v.y;
        a4.z += wgt * v.z; a4.w += wgt * v.w;
    }
    vred[tg][rv][d4] = a4;
    __syncthreads();
    if (tg == 0) {
        float4 s0 = vred[0][rv][d4];
        float4 s1 = vred[1][rv][d4];
        float4 s2 = vred[2][rv][d4];
        float4 s3 = vred[3][rv][d4];
        float4 o;
        o.x = s0.x + s1.x + s2.x + s3.x;
        o.y = s0.y + s1.y + s2.y + s3.y;
        o.z = s0.z + s1.z + s2.z + s3.z;
        o.w = s0.w + s1.w + s2.w + s3.w;
        *reinterpret_cast<float4*>(&g_attp[ts][b][g][rv][d4 * 4]) = o;
    }
    if (tid < REP) {
        g_attm[ts][b][g][tid] = rmax[tid];
        g_atts[ts][b][g][tid] = rsum[tid];
    }
}

// ---------------- Attention combine: grid (NKV, BATCH), 512 thr ----------------
__global__ void attn_combine_kernel()
{
    const int g   = blockIdx.x;
    const int b   = blockIdx.y;
    const int tid = threadIdx.x;
    const int d   = tid & (HD - 1);
    const int r   = tid >> 7;

    float M = -3.0e38f;
#pragma unroll
    for (int ts = 0; ts < TSPLIT; ts++) M = fmaxf(M, g_attm[ts][b][g][r]);

    float S = 0.f, a = 0.f;
#pragma unroll
    for (int ts = 0; ts < TSPLIT; ts++) {
        float f = __expf(g_attm[ts][b][g][r] - M);
        S += g_atts[ts][b][g][r] * f;
        a += g_attp[ts][b][g][r][d] * f;
    }
    g_att[(size_t)b * DIM + (g * REP + r) * HD + d] = a / S;
}

// ---------------- launch ----------------
extern "C" void kernel_launch(void* const* d_in, const int* in_sizes, int n_in,
                              void* d_out, int out_size)
{
    const float* x  = (const float*)d_in[0];
    const float* wq = (const float*)d_in[1];
    const float* wk = (const float*)d_in[2];
    const float* wv = (const float*)d_in[3];
    const float* wo = (const float*)d_in[4];
    const float* fc = (const float*)d_in[5];
    const float* fs = (const float*)d_in[6];
    const float* ck = (const float*)d_in[7];
    const float* cv = (const float*)d_in[8];
    const int*   sp = (const int*)d_in[9];

    int max_seq = in_sizes[7] / (BATCH * NKV * HD);

    gemm_qkv_kernel<<<dim3(QKV_N / 64, KSPLIT), 128>>>(x, wq, wk, wv);
    reduce_qkv_rope<<<(BATCH * (QKV_N / 2) + 255) / 256, 256>>>(fc, fs);
    attn_part_kernel<<<dim3(NKV, BATCH, TSPLIT), 512>>>(ck, cv, sp, max_seq);
    attn_combine_kernel<<<dim3(NKV, BATCH), 512>>>();
    gemm_o_kernel<<<dim3(DIM / 64, KSPLIT), 128>>>(wo);
    reduce_o<<<(BATCH * (DIM / 2) + 255) / 256, 256>>>((float*)d_out);
}

// round 9
// speedup vs baseline: 1.2540x; 1.2540x over previous
#include <cuda_runtime.h>
#include <cuda_bf16.h>
#include <math.h>

#define FULL_MASK 0xffffffffu

#define BATCH   32
#define DIM     4096
#define NQ      32
#define NKV     8
#define HD      128
#define QKV_N   6144
#define REP     4
#define KSPLIT  32
#define KLEN    (DIM / KSPLIT)   // 128
#define TSPLIT  16
#define CHUNK_MAX 128            // ceil(2048 / TSPLIT)

// Scratch (device globals; no allocation allowed)
__device__ float g_qkv[BATCH * QKV_N];                    // post-reduce, post-RoPE
__device__ float g_att[BATCH * DIM];                      // attention output, pre-wo
__device__ float g_part_qkv[KSPLIT][BATCH][QKV_N];        // split-K partials
__device__ float g_part_o[KSPLIT][BATCH][DIM];
__device__ float g_attp[TSPLIT][BATCH][NKV][REP][HD];     // split-T partial A*V (unnormalized)
__device__ float g_attm[TSPLIT][BATCH][NKV][REP];         // split-T local max
__device__ float g_atts[TSPLIT][BATCH][NKV][REP];         // split-T local expsum

// ---------------- packed fp32x2 helpers (Blackwell) ----------------
__device__ __forceinline__ unsigned long long pack2(float lo, float hi) {
    unsigned long long r;
    asm("mov.b64 %0, {%1, %2};" : "=l"(r) : "f"(lo), "f"(hi));
    return r;
}
__device__ __forceinline__ void fma2(unsigned long long& d, unsigned long long a, unsigned long long b) {
    asm("fma.rn.f32x2 %0, %1, %2, %0;" : "+l"(d) : "l"(a), "l"(b));
}
__device__ __forceinline__ float2 unpack2(unsigned long long v) {
    float lo, hi;
    asm("mov.b64 {%0, %1}, %2;" : "=f"(lo), "=f"(hi) : "l"(v));
    return make_float2(lo, hi);
}

// ---------------- Split-K skinny GEMM tile (proven shape) ----------------
// M = 32 rows, N-tile = 64 cols, 128 threads, 2 cols per thread.
__device__ __forceinline__ void gemm_tile(const float* __restrict__ A,
                                          const float* __restrict__ W,
                                          float* __restrict__ C,
                                          int K, int ldc, int wrow0, int ccol0,
                                          int kbeg)
{
    __shared__ __align__(16) float As[32][34];   // [kk][m]
    __shared__ float Ws[32][65];                 // [kk][n]

    const int tid   = threadIdx.x;
    const int c     = tid & 31;
    const int rbase = (tid >> 5) << 3;           // 0,8,16,24

    unsigned long long acc[4][2];
#pragma unroll
    for (int p = 0; p < 4; p++) { acc[p][0] = 0ull; acc[p][1] = 0ull; }

    for (int k0 = kbeg; k0 < kbeg + KLEN; k0 += 32) {
#pragma unroll
        for (int j = 0; j < 2; j++) {
            int e  = tid + j * 128;
            int m  = e >> 3;
            int kk = (e & 7) * 4;
            float4 v = *reinterpret_cast<const float4*>(&A[(size_t)m * K + k0 + kk]);
            As[kk + 0][m] = v.x; As[kk + 1][m] = v.y;
            As[kk + 2][m] = v.z; As[kk + 3][m] = v.w;
        }
#pragma unroll
        for (int j = 0; j < 4; j++) {
            int e  = tid + j * 128;
            int n  = e >> 3;
            int kk = (e & 7) * 4;
            float4 v = *reinterpret_cast<const float4*>(&W[(size_t)(wrow0 + n) * K + k0 + kk]);
            Ws[kk + 0][n] = v.x; Ws[kk + 1][n] = v.y;
            Ws[kk + 2][n] = v.z; Ws[kk + 3][n] = v.w;
        }
        __syncthreads();

#pragma unroll
        for (int kk = 0; kk < 32; kk++) {
            const unsigned long long* ap =
                reinterpret_cast<const unsigned long long*>(&As[kk][rbase]);
            unsigned long long a0 = ap[0], a1 = ap[1], a2 = ap[2], a3 = ap[3];
            float w0 = Ws[kk][c];
            float w1 = Ws[kk][c + 32];
            unsigned long long W0 = pack2(w0, w0);
            unsigned long long W1 = pack2(w1, w1);
            fma2(acc[0][0], a0, W0); fma2(acc[1][0], a1, W0);
            fma2(acc[2][0], a2, W0); fma2(acc[3][0], a3, W0);
            fma2(acc[0][1], a0, W1); fma2(acc[1][1], a1, W1);
            fma2(acc[2][1], a2, W1); fma2(acc[3][1], a3, W1);
        }
        __syncthreads();
    }

#pragma unroll
    for (int p = 0; p < 4; p++) {
#pragma unroll
        for (int cc = 0; cc < 2; cc++) {
            float2 v = unpack2(acc[p][cc]);
            int m   = rbase + 2 * p;
            int col = ccol0 + c + 32 * cc;
            C[(size_t)m * ldc + col]       = v.x;
            C[(size_t)(m + 1) * ldc + col] = v.y;
        }
    }
}

__global__ void gemm_qkv_kernel(const float* __restrict__ x,
                                const float* __restrict__ wq,
                                const float* __restrict__ wk,
                                const float* __restrict__ wv)
{
    int n0 = blockIdx.x * 64;
    int kbeg = blockIdx.y * KLEN;
    const float* W;
    int wrow0;
    if (n0 < 4096)      { W = wq; wrow0 = n0; }
    else if (n0 < 5120) { W = wk; wrow0 = n0 - 4096; }
    else                { W = wv; wrow0 = n0 - 5120; }
    gemm_tile(x, W, &g_part_qkv[blockIdx.y][0][0], DIM, QKV_N, wrow0, n0, kbeg);
}

__global__ void gemm_o_kernel(const float* __restrict__ wo)
{
    int n0 = blockIdx.x * 64;
    int kbeg = blockIdx.y * KLEN;
    gemm_tile(g_att, wo, &g_part_o[blockIdx.y][0][0], DIM, DIM, n0, n0, kbeg);
}

// ---------------- QKV reduce + fused RoPE ----------------
__global__ void reduce_qkv_rope(const float* __restrict__ cosv,
                                const float* __restrict__ sinv)
{
    int idx = blockIdx.x * 256 + threadIdx.x;
    if (idx >= BATCH * (QKV_N / 2)) return;
    int b  = idx / (QKV_N / 2);
    int pr = idx - b * (QKV_N / 2);
    int col = pr * 2;

    float sx = 0.f, sy = 0.f;
#pragma unroll 8
    for (int ks = 0; ks < KSPLIT; ks++) {
        float2 v = *reinterpret_cast<const float2*>(&g_part_qkv[ks][b][col]);
        sx += v.x; sy += v.y;
    }
    float2 o;
    if (col < 5120) {
        int d2 = (col & (HD - 1)) >> 1;
        float c = cosv[d2], s = sinv[d2];
        o.x = sx * c - sy * s;
        o.y = sx * s + sy * c;
    } else {
        o.x = sx; o.y = sy;
    }
    *reinterpret_cast<float2*>(&g_qkv[(size_t)b * QKV_N + col]) = o;
}

__global__ void reduce_o(float* __restrict__ out)
{
    int idx = blockIdx.x * 256 + threadIdx.x;
    if (idx >= BATCH * (DIM / 2)) return;
    int b  = idx / (DIM / 2);
    int pr = idx - b * (DIM / 2);
    int col = pr * 2;
    float sx = 0.f, sy = 0.f;
#pragma unroll 8
    for (int ks = 0; ks < KSPLIT; ks++) {
        float2 v = *reinterpret_cast<const float2*>(&g_part_o[ks][b][col]);
        sx += v.x; sy += v.y;
    }
    *reinterpret_cast<float2*>(&out[(size_t)b * DIM + col]) = make_float2(sx, sy);
}

// ---------------- Attention partials: grid (NKV, BATCH, TSPLIT), 512 thr ----------------
__global__ void __launch_bounds__(512, 2)
attn_part_kernel(const float* __restrict__ cache_k,
                 const float* __restrict__ cache_v,
                 const int* __restrict__ sp_ptr,
                 int max_seq)
{
    const int g    = blockIdx.x;
    const int b    = blockIdx.y;
    const int ts   = blockIdx.z;
    const int tid  = threadIdx.x;     // 0..511
    const int lane = tid & 31;
    const int w    = tid >> 5;        // 0..15
    const int sp   = *sp_ptr;
    const int T    = sp + 1;
    const int chunk = (T + TSPLIT - 1) / TSPLIT;
    const int t0   = ts * chunk;
    const int t1   = min(t0 + chunk, T);

    // V-phase thread mapping: t-quarter x dim
    const int dv = tid & (HD - 1);    // 0..127
    const int tq = tid >> 7;          // 0..3

    if (t0 >= T) {     // empty split
        if (tid < REP) { g_attm[ts][b][g][tid] = -3.0e38f; g_atts[ts][b][g][tid] = 0.f; }
        if (tq == 0)
#pragma unroll
            for (int r = 0; r < REP; r++) g_attp[ts][b][g][r][dv] = 0.f;
        return;
    }
    const int n = t1 - t0;            // <= CHUNK_MAX

    __shared__ float sc[REP][CHUNK_MAX];
    __shared__ float q4s[REP][HD];
    __shared__ float redm[REP][4];
    __shared__ float reds[REP][4];
    __shared__ float rmax[REP];
    __shared__ float rsum[REP];
    __shared__ float vred[4][REP][HD];   // 8KB tq-reduction

    for (int i = tid; i < REP * HD; i += 512) {
        int rr = i >> 7, dd = i & (HD - 1);
        q4s[rr][dd] = g_qkv[(size_t)b * QKV_N + (g * REP + rr) * HD + dd];
    }
    __syncthreads();

    float4 q0 = reinterpret_cast<const float4*>(q4s[0])[lane];
    float4 q1 = reinterpret_cast<const float4*>(q4s[1])[lane];
    float4 q2 = reinterpret_cast<const float4*>(q4s[2])[lane];
    float4 q3 = reinterpret_cast<const float4*>(q4s[3])[lane];

    const float* knew = &g_qkv[(size_t)b * QKV_N + 4096 + g * HD];
    const float* vnew = &g_qkv[(size_t)b * QKV_N + 5120 + g * HD];
    const float scale = 0.08838834764831845f;   // 1/sqrt(128)

    // ---- scores: warp-per-t across 16 warps (proven 359.2 shape) ----
    for (int t = t0 + w; t < t1; t += 16) {
        const float* kp = (t < sp)
            ? &cache_k[(((size_t)b * max_seq + t) * NKV + g) * HD]
            : knew;
        float4 kv = reinterpret_cast<const float4*>(kp)[lane];
        float p0 = q0.x*kv.x + q0.y*kv.y + q0.z*kv.z + q0.w*kv.w;
        float p1 = q1.x*kv.x + q1.y*kv.y + q1.z*kv.z + q1.w*kv.w;
        float p2 = q2.x*kv.x + q2.y*kv.y + q2.z*kv.z + q2.w*kv.w;
        float p3 = q3.x*kv.x + q3.y*kv.y + q3.z*kv.z + q3.w*kv.w;
#pragma unroll
        for (int off = 16; off; off >>= 1) {
            p0 += __shfl_xor_sync(FULL_MASK, p0, off);
            p1 += __shfl_xor_sync(FULL_MASK, p1, off);
            p2 += __shfl_xor_sync(FULL_MASK, p2, off);
            p3 += __shfl_xor_sync(FULL_MASK, p3, off);
        }
        if (lane == 0) {
            sc[0][t - t0] = p0 * scale; sc[1][t - t0] = p1 * scale;
            sc[2][t - t0] = p2 * scale; sc[3][t - t0] = p3 * scale;
        }
    }
    __syncthreads();

    // ---- local softmax: all 4 reps in parallel (128 threads per rep) ----
    {
        const int rr  = tid >> 7;
        const int tt  = tid & 127;
        const int wq4 = (tid >> 5) & 3;

        float mv = (tt < n) ? sc[rr][tt] : -3.0e38f;
#pragma unroll
        for (int off = 16; off; off >>= 1) mv = fmaxf(mv, __shfl_xor_sync(FULL_MASK, mv, off));
        if (lane == 0) redm[rr][wq4] = mv;
        __syncthreads();
        float m = fmaxf(fmaxf(redm[rr][0], redm[rr][1]),
                        fmaxf(redm[rr][2], redm[rr][3]));

        float e = 0.f;
        if (tt < n) {
            e = __expf(sc[rr][tt] - m);
            sc[rr][tt] = e;
        }
        float s = e;
#pragma unroll
        for (int off = 16; off; off >>= 1) s += __shfl_xor_sync(FULL_MASK, s, off);
        if (lane == 0) reds[rr][wq4] = s;
        __syncthreads();
        if (tt == 0) {
            rmax[rr] = m;
            rsum[rr] = reds[rr][0] + reds[rr][1] + reds[rr][2] + reds[rr][3];
        }
    }
    __syncthreads();

    // ---- partial A @ V: thread (tq, dv); each V value loaded ONCE,
    //      all 4 reps accumulated in registers ----
    float a0 = 0.f, a1 = 0.f, a2 = 0.f, a3 = 0.f;
#pragma unroll 4
    for (int t = t0 + tq; t < t1; t += 4) {
        const float* vp = (t < sp)
            ? &cache_v[(((size_t)b * max_seq + t) * NKV + g) * HD]
            : vnew;
        float v = vp[dv];
        int tt = t - t0;
        a0 += sc[0][tt] * v;
        a1 += sc[1][tt] * v;
        a2 += sc[2][tt] * v;
        a3 += sc[3][tt] * v;
    }
    vred[tq][0][dv] = a0;
    vred[tq][1][dv] = a1;
    vred[tq][2][dv] = a2;
    vred[tq][3][dv] = a3;
    __syncthreads();
    if (tq == 0) {
#pragma unroll
        for (int r = 0; r < REP; r++) {
            float o = vred[0][r][dv] + vred[1][r][dv]
                    + vred[2][r][dv] + vred[3][r][dv];
            g_attp[ts][b][g][r][dv] = o;
        }
    }
    if (tid < REP) {
        g_attm[ts][b][g][tid] = rmax[tid];
        g_atts[ts][b][g][tid] = rsum[tid];
    }
}

// ---------------- Attention combine: grid (NKV, BATCH), 512 thr ----------------
__global__ void attn_combine_kernel()
{
    const int g   = blockIdx.x;
    const int b   = blockIdx.y;
    const int tid = threadIdx.x;
    const int d   = tid & (HD - 1);
    const int r   = tid >> 7;

    float M = -3.0e38f;
#pragma unroll
    for (int ts = 0; ts < TSPLIT; ts++) M = fmaxf(M, g_attm[ts][b][g][r]);

    float S = 0.f, a = 0.f;
#pragma unroll
    for (int ts = 0; ts < TSPLIT; ts++) {
        float f = __expf(g_attm[ts][b][g][r] - M);
        S += g_atts[ts][b][g][r] * f;
        a += g_attp[ts][b][g][r][d] * f;
    }
    g_att[(size_t)b * DIM + (g * REP + r) * HD + d] = a / S;
}

// ---------------- launch ----------------
extern "C" void kernel_launch(void* const* d_in, const int* in_sizes, int n_in,
                              void* d_out, int out_size)
{
    const float* x  = (const float*)d_in[0];
    const float* wq = (const float*)d_in[1];
    const float* wk = (const float*)d_in[2];
    const float* wv = (const float*)d_in[3];
    const float* wo = (const float*)d_in[4];
    const float* fc = (const float*)d_in[5];
    const float* fs = (const float*)d_in[6];
    const float* ck = (const float*)d_in[7];
    const float* cv = (const float*)d_in[8];
    const int*   sp = (const int*)d_in[9];

    int max_seq = in_sizes[7] / (BATCH * NKV * HD);

    gemm_qkv_kernel<<<dim3(QKV_N / 64, KSPLIT), 128>>>(x, wq, wk, wv);
    reduce_qkv_rope<<<(BATCH * (QKV_N / 2) + 255) / 256, 256>>>(fc, fs);
    attn_part_kernel<<<dim3(NKV, BATCH, TSPLIT), 512>>>(ck, cv, sp, max_seq);
    attn_combine_kernel<<<dim3(NKV, BATCH), 512>>>();
    gemm_o_kernel<<<dim3(DIM / 64, KSPLIT), 128>>>(wo);
    reduce_o<<<(BATCH * (DIM / 2) + 255) / 256, 256>>>((float*)d_out);
}

// round 10
// speedup vs baseline: 1.4318x; 1.1419x over previous
#include <cuda_runtime.h>
#include <cuda_bf16.h>
#include <math.h>

#define FULL_MASK 0xffffffffu

#define BATCH   32
#define DIM     4096
#define NQ      32
#define NKV     8
#define HD      128
#define QKV_N   6144
#define REP     4
#define KSPLIT  32
#define KLEN    (DIM / KSPLIT)   // 128
#define TSPLIT  16
#define CHUNK_MAX 128            // ceil(2048 / TSPLIT)

// Scratch (device globals; no allocation allowed)
__device__ float g_qkv[BATCH * QKV_N];                    // post-reduce, post-RoPE
__device__ float g_att[BATCH * DIM];                      // attention output, pre-wo
__device__ float g_part_qkv[KSPLIT][BATCH][QKV_N];        // split-K partials
__device__ float g_part_o[KSPLIT][BATCH][DIM];
__device__ float g_attp[TSPLIT][BATCH][NKV][REP][HD];     // split-T partial A*V (unnormalized)
__device__ float g_attm[TSPLIT][BATCH][NKV][REP];         // split-T local max
__device__ float g_atts[TSPLIT][BATCH][NKV][REP];         // split-T local expsum

// ---------------- packed fp32x2 helpers (Blackwell) ----------------
__device__ __forceinline__ unsigned long long pack2(float lo, float hi) {
    unsigned long long r;
    asm("mov.b64 %0, {%1, %2};" : "=l"(r) : "f"(lo), "f"(hi));
    return r;
}
__device__ __forceinline__ void fma2(unsigned long long& d, unsigned long long a, unsigned long long b) {
    asm("fma.rn.f32x2 %0, %1, %2, %0;" : "+l"(d) : "l"(a), "l"(b));
}
__device__ __forceinline__ float2 unpack2(unsigned long long v) {
    float lo, hi;
    asm("mov.b64 {%0, %1}, %2;" : "=f"(lo), "=f"(hi) : "l"(v));
    return make_float2(lo, hi);
}

// ---------------- Split-K skinny GEMM tile (proven shape) ----------------
// M = 32 rows, N-tile = 64 cols, 128 threads, 2 cols per thread.
__device__ __forceinline__ void gemm_tile(const float* __restrict__ A,
                                          const float* __restrict__ W,
                                          float* __restrict__ C,
                                          int K, int ldc, int wrow0, int ccol0,
                                          int kbeg)
{
    __shared__ __align__(16) float As[32][34];   // [kk][m]
    __shared__ float Ws[32][65];                 // [kk][n]

    const int tid   = threadIdx.x;
    const int c     = tid & 31;
    const int rbase = (tid >> 5) << 3;           // 0,8,16,24

    unsigned long long acc[4][2];
#pragma unroll
    for (int p = 0; p < 4; p++) { acc[p][0] = 0ull; acc[p][1] = 0ull; }

    for (int k0 = kbeg; k0 < kbeg + KLEN; k0 += 32) {
#pragma unroll
        for (int j = 0; j < 2; j++) {
            int e  = tid + j * 128;
            int m  = e >> 3;
            int kk = (e & 7) * 4;
            float4 v = *reinterpret_cast<const float4*>(&A[(size_t)m * K + k0 + kk]);
            As[kk + 0][m] = v.x; As[kk + 1][m] = v.y;
            As[kk + 2][m] = v.z; As[kk + 3][m] = v.w;
        }
#pragma unroll
        for (int j = 0; j < 4; j++) {
            int e  = tid + j * 128;
            int n  = e >> 3;
            int kk = (e & 7) * 4;
            float4 v = *reinterpret_cast<const float4*>(&W[(size_t)(wrow0 + n) * K + k0 + kk]);
            Ws[kk + 0][n] = v.x; Ws[kk + 1][n] = v.y;
            Ws[kk + 2][n] = v.z; Ws[kk + 3][n] = v.w;
        }
        __syncthreads();

#pragma unroll
        for (int kk = 0; kk < 32; kk++) {
            const unsigned long long* ap =
                reinterpret_cast<const unsigned long long*>(&As[kk][rbase]);
            unsigned long long a0 = ap[0], a1 = ap[1], a2 = ap[2], a3 = ap[3];
            float w0 = Ws[kk][c];
            float w1 = Ws[kk][c + 32];
            unsigned long long W0 = pack2(w0, w0);
            unsigned long long W1 = pack2(w1, w1);
            fma2(acc[0][0], a0, W0); fma2(acc[1][0], a1, W0);
            fma2(acc[2][0], a2, W0); fma2(acc[3][0], a3, W0);
            fma2(acc[0][1], a0, W1); fma2(acc[1][1], a1, W1);
            fma2(acc[2][1], a2, W1); fma2(acc[3][1], a3, W1);
        }
        __syncthreads();
    }

#pragma unroll
    for (int p = 0; p < 4; p++) {
#pragma unroll
        for (int cc = 0; cc < 2; cc++) {
            float2 v = unpack2(acc[p][cc]);
            int m   = rbase + 2 * p;
            int col = ccol0 + c + 32 * cc;
            C[(size_t)m * ldc + col]       = v.x;
            C[(size_t)(m + 1) * ldc + col] = v.y;
        }
    }
}

__global__ void gemm_qkv_kernel(const float* __restrict__ x,
                                const float* __restrict__ wq,
                                const float* __restrict__ wk,
                                const float* __restrict__ wv)
{
    int n0 = blockIdx.x * 64;
    int kbeg = blockIdx.y * KLEN;
    const float* W;
    int wrow0;
    if (n0 < 4096)      { W = wq; wrow0 = n0; }
    else if (n0 < 5120) { W = wk; wrow0 = n0 - 4096; }
    else                { W = wv; wrow0 = n0 - 5120; }
    gemm_tile(x, W, &g_part_qkv[blockIdx.y][0][0], DIM, QKV_N, wrow0, n0, kbeg);
}

__global__ void gemm_o_kernel(const float* __restrict__ wo)
{
    int n0 = blockIdx.x * 64;
    int kbeg = blockIdx.y * KLEN;
    gemm_tile(g_att, wo, &g_part_o[blockIdx.y][0][0], DIM, DIM, n0, n0, kbeg);
}

// ---------------- QKV reduce + fused RoPE ----------------
__global__ void reduce_qkv_rope(const float* __restrict__ cosv,
                                const float* __restrict__ sinv)
{
    int idx = blockIdx.x * 256 + threadIdx.x;
    if (idx >= BATCH * (QKV_N / 2)) return;
    int b  = idx / (QKV_N / 2);
    int pr = idx - b * (QKV_N / 2);
    int col = pr * 2;

    float sx = 0.f, sy = 0.f;
#pragma unroll 8
    for (int ks = 0; ks < KSPLIT; ks++) {
        float2 v = *reinterpret_cast<const float2*>(&g_part_qkv[ks][b][col]);
        sx += v.x; sy += v.y;
    }
    float2 o;
    if (col < 5120) {
        int d2 = (col & (HD - 1)) >> 1;
        float c = cosv[d2], s = sinv[d2];
        o.x = sx * c - sy * s;
        o.y = sx * s + sy * c;
    } else {
        o.x = sx; o.y = sy;
    }
    *reinterpret_cast<float2*>(&g_qkv[(size_t)b * QKV_N + col]) = o;
}

__global__ void reduce_o(float* __restrict__ out)
{
    int idx = blockIdx.x * 256 + threadIdx.x;
    if (idx >= BATCH * (DIM / 2)) return;
    int b  = idx / (DIM / 2);
    int pr = idx - b * (DIM / 2);
    int col = pr * 2;
    float sx = 0.f, sy = 0.f;
#pragma unroll 8
    for (int ks = 0; ks < KSPLIT; ks++) {
        float2 v = *reinterpret_cast<const float2*>(&g_part_o[ks][b][col]);
        sx += v.x; sy += v.y;
    }
    *reinterpret_cast<float2*>(&out[(size_t)b * DIM + col]) = make_float2(sx, sy);
}

// ---------------- Attention partials: grid (NKV, BATCH, TSPLIT), 512 thr ----------------
__global__ void __launch_bounds__(512, 2)
attn_part_kernel(const float* __restrict__ cache_k,
                 const float* __restrict__ cache_v,
                 const int* __restrict__ sp_ptr,
                 int max_seq)
{
    const int g    = blockIdx.x;
    const int b    = blockIdx.y;
    const int ts   = blockIdx.z;
    const int tid  = threadIdx.x;     // 0..511
    const int lane = tid & 31;
    const int w    = tid >> 5;        // 0..15
    const int sp   = *sp_ptr;
    const int T    = sp + 1;
    const int chunk = (T + TSPLIT - 1) / TSPLIT;
    const int t0   = ts * chunk;
    const int t1   = min(t0 + chunk, T);

    // V-phase thread mapping: t-quarter x dim
    const int dv = tid & (HD - 1);    // 0..127
    const int tq = tid >> 7;          // 0..3

    if (t0 >= T) {     // empty split
        if (tid < REP) { g_attm[ts][b][g][tid] = -3.0e38f; g_atts[ts][b][g][tid] = 0.f; }
        if (tq == 0)
#pragma unroll
            for (int r = 0; r < REP; r++) g_attp[ts][b][g][r][dv] = 0.f;
        return;
    }
    const int n = t1 - t0;            // <= CHUNK_MAX

    __shared__ float sc[REP][CHUNK_MAX];
    __shared__ float q4s[REP][HD];
    __shared__ float redm[REP][4];
    __shared__ float reds[REP][4];
    __shared__ float rmax[REP];
    __shared__ float rsum[REP];
    __shared__ float vred[4][REP][HD];   // 8KB tq-reduction

    for (int i = tid; i < REP * HD; i += 512) {
        int rr = i >> 7, dd = i & (HD - 1);
        q4s[rr][dd] = g_qkv[(size_t)b * QKV_N + (g * REP + rr) * HD + dd];
    }
    __syncthreads();

    float4 q0 = reinterpret_cast<const float4*>(q4s[0])[lane];
    float4 q1 = reinterpret_cast<const float4*>(q4s[1])[lane];
    float4 q2 = reinterpret_cast<const float4*>(q4s[2])[lane];
    float4 q3 = reinterpret_cast<const float4*>(q4s[3])[lane];

    const float* knew = &g_qkv[(size_t)b * QKV_N + 4096 + g * HD];
    const float* vnew = &g_qkv[(size_t)b * QKV_N + 5120 + g * HD];
    const float scale = 0.08838834764831845f;   // 1/sqrt(128)

    // ---- scores: warp-per-t, 2-stage prefetch + 6-shuffle reduction ----
    {
        int t = t0 + w;
        float4 kc;
        if (t < t1) {
            const float* kp = (t < sp)
                ? &cache_k[(((size_t)b * max_seq + t) * NKV + g) * HD]
                : knew;
            kc = reinterpret_cast<const float4*>(kp)[lane];
        }
        for (; t < t1; t += 16) {
            // prefetch next t for this warp
            const int tn = t + 16;
            float4 kn;
            if (tn < t1) {
                const float* kp2 = (tn < sp)
                    ? &cache_k[(((size_t)b * max_seq + tn) * NKV + g) * HD]
                    : knew;
                kn = reinterpret_cast<const float4*>(kp2)[lane];
            }

            float p0 = q0.x*kc.x + q0.y*kc.y + q0.z*kc.z + q0.w*kc.w;
            float p1 = q1.x*kc.x + q1.y*kc.y + q1.z*kc.z + q1.w*kc.w;
            float p2 = q2.x*kc.x + q2.y*kc.y + q2.z*kc.z + q2.w*kc.w;
            float p3 = q3.x*kc.x + q3.y*kc.y + q3.z*kc.z + q3.w*kc.w;

            // round 16: route p0/p1 and p2/p3 into half-warps
            float x01 = (lane & 16) ? p1 : p0;
            float z01 = (lane & 16) ? p0 : p1;
            float s01 = x01 + __shfl_xor_sync(FULL_MASK, z01, 16);
            float x23 = (lane & 16) ? p3 : p2;
            float z23 = (lane & 16) ? p2 : p3;
            float s23 = x23 + __shfl_xor_sync(FULL_MASK, z23, 16);
            // round 8: route into 8-lane groups (0-7:p0, 8-15:p2, 16-23:p1, 24-31:p3)
            float xx = (lane & 8) ? s23 : s01;
            float zz = (lane & 8) ? s01 : s23;
            float v  = xx + __shfl_xor_sync(FULL_MASK, zz, 8);
            // rounds 4,2,1 within 8-lane groups
            v += __shfl_xor_sync(FULL_MASK, v, 4);
            v += __shfl_xor_sync(FULL_MASK, v, 2);
            v += __shfl_xor_sync(FULL_MASK, v, 1);

            if ((lane & 7) == 0) {
                int r = ((lane >> 4) & 1) | (((lane >> 3) & 1) << 1);  // 0->0, 8->2, 16->1, 24->3
                sc[r][t - t0] = v * scale;
            }
            kc = kn;
        }
    }
    __syncthreads();

    // ---- local softmax: all 4 reps in parallel (128 threads per rep) ----
    {
        const int rr  = tid >> 7;
        const int tt  = tid & 127;
        const int wq4 = (tid >> 5) & 3;

        float mv = (tt < n) ? sc[rr][tt] : -3.0e38f;
#pragma unroll
        for (int off = 16; off; off >>= 1) mv = fmaxf(mv, __shfl_xor_sync(FULL_MASK, mv, off));
        if (lane == 0) redm[rr][wq4] = mv;
        __syncthreads();
        float m = fmaxf(fmaxf(redm[rr][0], redm[rr][1]),
                        fmaxf(redm[rr][2], redm[rr][3]));

        float e = 0.f;
        if (tt < n) {
            e = __expf(sc[rr][tt] - m);
            sc[rr][tt] = e;
        }
        float s = e;
#pragma unroll
        for (int off = 16; off; off >>= 1) s += __shfl_xor_sync(FULL_MASK, s, off);
        if (lane == 0) reds[rr][wq4] = s;
        __syncthreads();
        if (tt == 0) {
            rmax[rr] = m;
            rsum[rr] = reds[rr][0] + reds[rr][1] + reds[rr][2] + reds[rr][3];
        }
    }
    __syncthreads();

    // ---- partial A @ V: thread (tq, dv); each V value loaded ONCE,
    //      all 4 reps accumulated in registers ----
    float a0 = 0.f, a1 = 0.f, a2 = 0.f, a3 = 0.f;
#pragma unroll 8
    for (int t = t0 + tq; t < t1; t += 4) {
        const float* vp = (t < sp)
            ? &cache_v[(((size_t)b * max_seq + t) * NKV + g) * HD]
            : vnew;
        float v = vp[dv];
        int tt = t - t0;
        a0 += sc[0][tt] * v;
        a1 += sc[1][tt] * v;
        a2 += sc[2][tt] * v;
        a3 += sc[3][tt] * v;
    }
    vred[tq][0][dv] = a0;
    vred[tq][1][dv] = a1;
    vred[tq][2][dv] = a2;
    vred[tq][3][dv] = a3;
    __syncthreads();
    if (tq == 0) {
#pragma unroll
        for (int r = 0; r < REP; r++) {
            float o = vred[0][r][dv] + vred[1][r][dv]
                    + vred[2][r][dv] + vred[3][r][dv];
            g_attp[ts][b][g][r][dv] = o;
        }
    }
    if (tid < REP) {
        g_attm[ts][b][g][tid] = rmax[tid];
        g_atts[ts][b][g][tid] = rsum[tid];
    }
}

// ---------------- Attention combine: grid (NKV, BATCH), 512 thr ----------------
__global__ void attn_combine_kernel()
{
    const int g   = blockIdx.x;
    const int b   = blockIdx.y;
    const int tid = threadIdx.x;
    const int d   = tid & (HD - 1);
    const int r   = tid >> 7;

    float M = -3.0e38f;
#pragma unroll
    for (int ts = 0; ts < TSPLIT; ts++) M = fmaxf(M, g_attm[ts][b][g][r]);

    float S = 0.f, a = 0.f;
#pragma unroll
    for (int ts = 0; ts < TSPLIT; ts++) {
        float f = __expf(g_attm[ts][b][g][r] - M);
        S += g_atts[ts][b][g][r] * f;
        a += g_attp[ts][b][g][r][d] * f;
    }
    g_att[(size_t)b * DIM + (g * REP + r) * HD + d] = a / S;
}

// ---------------- launch ----------------
extern "C" void kernel_launch(void* const* d_in, const int* in_sizes, int n_in,
                              void* d_out, int out_size)
{
    const float* x  = (const float*)d_in[0];
    const float* wq = (const float*)d_in[1];
    const float* wk = (const float*)d_in[2];
    const float* wv = (const float*)d_in[3];
    const float* wo = (const float*)d_in[4];
    const float* fc = (const float*)d_in[5];
    const float* fs = (const float*)d_in[6];
    const float* ck = (const float*)d_in[7];
    const float* cv = (const float*)d_in[8];
    const int*   sp = (const int*)d_in[9];

    int max_seq = in_sizes[7] / (BATCH * NKV * HD);

    gemm_qkv_kernel<<<dim3(QKV_N / 64, KSPLIT), 128>>>(x, wq, wk, wv);
    reduce_qkv_rope<<<(BATCH * (QKV_N / 2) + 255) / 256, 256>>>(fc, fs);
    attn_part_kernel<<<dim3(NKV, BATCH, TSPLIT), 512>>>(ck, cv, sp, max_seq);
    attn_combine_kernel<<<dim3(NKV, BATCH), 512>>>();
    gemm_o_kernel<<<dim3(DIM / 64, KSPLIT), 128>>>(wo);
    reduce_o<<<(BATCH * (DIM / 2) + 255) / 256, 256>>>((float*)d_out);
}